// round 8
// baseline (speedup 1.0000x reference)
#include <cuda_runtime.h>
#include <cuda_bf16.h>
#include <cuda_fp16.h>
#include <cstdint>

#define MAXN 100000
#define MAXE 3200000
#define FDIM 128
#define HDIM 64
#define H2DIM 128
#define MAXG 256
#define GROWS 128   // rows per GEMM block tile

// ---------------- device scratch (static, no allocation) ----------------
__device__ __align__(16) float d_h[(size_t)MAXN * HDIM];
__device__ __align__(16) __half d_t[(size_t)MAXN * H2DIM];   // fp16 intermediate
__device__ __align__(16) __half d_rh[(size_t)MAXN * HDIM];   // relu(aff(h)) as fp16
__device__ int   d_deg[MAXN];
__device__ int   d_off[MAXN];
__device__ int   d_cur[MAXN];
__device__ int   d_csr[MAXE];
__device__ int   d_bsum[256];
__device__ int   d_boff[256];
__device__ __align__(16) float d_statTS[3 * H2DIM];
__device__ __align__(16) float d_statTQ[3 * H2DIM];
__device__ __align__(16) float d_statHS[3 * HDIM];
__device__ __align__(16) float d_statHQ[3 * HDIM];
__device__ __align__(16) float d_sc1[H2DIM];
__device__ __align__(16) float d_sh1[H2DIM];
__device__ __align__(16) float d_scE[2 * HDIM];
__device__ __align__(16) float d_shE[2 * HDIM];
__device__ unsigned d_gmax[MAXG];
__device__ float d_wsum[MAXG];
__device__ __align__(16) float d_poolS[MAXG * HDIM];
__device__ float d_gate[MAXN];

// ---------------- init ----------------
__global__ void k_init(int n, int G) {
    int stride = gridDim.x * blockDim.x;
    int i0 = blockIdx.x * blockDim.x + threadIdx.x;
    for (int i = i0; i < n; i += stride) d_deg[i] = 0;
    for (int i = i0; i < 3 * H2DIM; i += stride) { d_statTS[i] = 0.f; d_statTQ[i] = 0.f; }
    for (int i = i0; i < 3 * HDIM; i += stride) { d_statHS[i] = 0.f; d_statHQ[i] = 0.f; }
    for (int i = i0; i < G; i += stride) { d_gmax[i] = 0u; d_wsum[i] = 0.f; }
    for (int i = i0; i < G * HDIM; i += stride) d_poolS[i] = 0.f;
}

// ---------------- CSR build ----------------
__global__ void k_hist(const int* __restrict__ dst, int e) {
    int i = blockIdx.x * blockDim.x + threadIdx.x;
    if (i < e) atomicAdd(&d_deg[dst[i]], 1);
}

__global__ void k_scan1(int n) {
    __shared__ int s[1024];
    int i = blockIdx.x * 1024 + threadIdx.x;
    int v = (i < n) ? d_deg[i] : 0;
    s[threadIdx.x] = v;
    __syncthreads();
    for (int d = 1; d < 1024; d <<= 1) {
        int t = 0;
        if ((int)threadIdx.x >= d) t = s[threadIdx.x - d];
        __syncthreads();
        s[threadIdx.x] += t;
        __syncthreads();
    }
    if (i < n) d_off[i] = s[threadIdx.x] - v;
    if (threadIdx.x == 1023) d_bsum[blockIdx.x] = s[1023];
}

__global__ void k_scan2(int nb) {
    int t = threadIdx.x;
    int v = (t < nb) ? d_bsum[t] : 0;
    int orig = v;
    for (int d = 1; d < 32; d <<= 1) {
        int u = __shfl_up_sync(0xffffffffu, v, d);
        if ((t & 31) >= d) v += u;
    }
    __shared__ int ws[4];
    if ((t & 31) == 31) ws[t >> 5] = v;
    __syncthreads();
    int add = 0;
    for (int w = 0; w < (t >> 5); w++) add += ws[w];
    if (t < nb) d_boff[t] = v + add - orig;
}

__global__ void k_scan3(int n) {
    int i = blockIdx.x * blockDim.x + threadIdx.x;
    if (i < n) {
        int v = d_off[i] + d_boff[i >> 10];
        d_off[i] = v;
        d_cur[i] = v;
    }
}

__global__ void k_scatter(const int* __restrict__ src, const int* __restrict__ dst, int e) {
    int i = blockIdx.x * blockDim.x + threadIdx.x;
    if (i < e) {
        int d = dst[i];
        int p = atomicAdd(&d_cur[d], 1);
        d_csr[p] = src[i];
    }
}

// ---------------- prep: d_rh = fp16(relu(scE[idx]*h + shE[idx])) ----------------
__global__ void k_prep(int affineIdx, int n) {
    int i = blockIdx.x * blockDim.x + threadIdx.x;
    if (i >= n * (HDIM / 2)) return;
    int c = i & (HDIM / 2 - 1);
    float2 v = ((const float2*)d_h)[i];
    float2 s2 = *(const float2*)(d_scE + affineIdx * HDIM + c * 2);
    float2 h2 = *(const float2*)(d_shE + affineIdx * HDIM + c * 2);
    float rx = fmaxf(fmaf(s2.x, v.x, h2.x), 0.f);
    float ry = fmaxf(fmaf(s2.y, v.y, h2.y), 0.f);
    ((__half2*)d_rh)[i] = __floats2half2_rn(rx, ry);
}

// ---------------- HMMA GEMM: out[n,N] = act(A[n,K]) @ W[K,N] + bias ----------------
// 3-term bf16 split: D = Ahi@Bhi + Alo@Bhi + Ahi@Blo, fp32 accum (mma.sync m16n8k16).
// ASRC: 0=Apar fp32, 2=d_t fp16 (+TRANS), 3=fused GIN gather (K=64 only)
// ODST: 0=d_h fp32, 1=d_t fp16
// STAT: 0 none, 1 statT, 2 statH.  emit_rh: write d_rh=fp16(relu(out)) (N=64 only).
__device__ __forceinline__ uint32_t bfpack(float x, float y) {
    __nv_bfloat16 bx = __float2bfloat16(x), by = __float2bfloat16(y);
    return ((uint32_t)__bfloat16_as_ushort(by) << 16) | __bfloat16_as_ushort(bx);
}

template <int K, int N, int ASRC, int ODST, bool TRANS, int STAT>
__global__ void __launch_bounds__(256)
k_gemm_mma(const float* __restrict__ Apar, const float* __restrict__ W,
           const float* __restrict__ bias, int layer, int n, int emit_rh,
           const float* __restrict__ epsArr, int affineIdx) {
    constexpr int NT = N / 8;
    constexpr int LDIM = K + 8;
    constexpr int ASZ = GROWS * LDIM * 2;
    constexpr int BSZ = N * LDIM * 2;
    extern __shared__ __align__(16) char smem[];
    __nv_bfloat16* a_hi = (__nv_bfloat16*)(smem);
    __nv_bfloat16* a_lo = (__nv_bfloat16*)(smem + ASZ);
    __nv_bfloat16* b_hi = (__nv_bfloat16*)(smem + 2 * ASZ);
    __nv_bfloat16* b_lo = (__nv_bfloat16*)(smem + 2 * ASZ + BSZ);
    float* stS = (float*)(smem + 2 * ASZ + 2 * BSZ);   // [8][N]
    float* stQ = stS + 8 * N;

    int tid = threadIdx.x;
    int row0 = blockIdx.x * GROWS;

    // --- B tiles: W row-major [K][N] -> n-major bf16 hi/lo [N][LDIM] ---
    for (int idx = tid; idx < K * N; idx += 256) {
        int k = idx / N, nn = idx - k * N;
        float v = W[idx];
        __nv_bfloat16 h = __float2bfloat16(v);
        __nv_bfloat16 l = __float2bfloat16(v - __bfloat162float(h));
        b_hi[nn * LDIM + k] = h;
        b_lo[nn * LDIM + k] = l;
    }

    // --- A tile ---
    if (ASRC == 0) {
        const float* A = Apar;
        for (int idx = tid; idx < GROWS * K / 4; idx += 256) {
            int row = idx / (K / 4);
            int kf = (idx - row * (K / 4)) * 4;
            int grow = row0 + row;
            float4 v = make_float4(0.f, 0.f, 0.f, 0.f);
            if (grow < n) v = *(const float4*)(A + (size_t)grow * K + kf);
            float rx = v.x - __bfloat162float(__float2bfloat16(v.x));
            float ry = v.y - __bfloat162float(__float2bfloat16(v.y));
            float rz = v.z - __bfloat162float(__float2bfloat16(v.z));
            float rw = v.w - __bfloat162float(__float2bfloat16(v.w));
            __nv_bfloat16* ah = a_hi + row * LDIM + kf;
            __nv_bfloat16* al = a_lo + row * LDIM + kf;
            *(uint32_t*)(ah) = bfpack(v.x, v.y);
            *(uint32_t*)(ah + 2) = bfpack(v.z, v.w);
            *(uint32_t*)(al) = bfpack(rx, ry);
            *(uint32_t*)(al + 2) = bfpack(rz, rw);
        }
    } else if (ASRC == 2) {
        const __half* A = d_t;
        for (int idx = tid; idx < GROWS * K / 8; idx += 256) {
            int row = idx / (K / 8);
            int kf = (idx - row * (K / 8)) * 8;
            int grow = row0 + row;
            uint4 raw = make_uint4(0u, 0u, 0u, 0u);
            if (grow < n) raw = *(const uint4*)(A + (size_t)grow * K + kf);
            float v[8];
            {
                float2 p0 = __half22float2(*(__half2*)&raw.x);
                float2 p1 = __half22float2(*(((__half2*)&raw.x) + 1));
                float2 p2 = __half22float2(*(__half2*)&raw.z);
                float2 p3 = __half22float2(*(((__half2*)&raw.z) + 1));
                v[0] = p0.x; v[1] = p0.y; v[2] = p1.x; v[3] = p1.y;
                v[4] = p2.x; v[5] = p2.y; v[6] = p3.x; v[7] = p3.y;
            }
            if (TRANS) {
#pragma unroll
                for (int j = 0; j < 8; j++)
                    v[j] = fmaxf(fmaf(d_sc1[kf + j], v[j], d_sh1[kf + j]), 0.f);
            }
            __nv_bfloat16* ah = a_hi + row * LDIM + kf;
            __nv_bfloat16* al = a_lo + row * LDIM + kf;
#pragma unroll
            for (int j = 0; j < 4; j++) {
                float x = v[2 * j], y = v[2 * j + 1];
                float rx = x - __bfloat162float(__float2bfloat16(x));
                float ry = y - __bfloat162float(__float2bfloat16(y));
                *(uint32_t*)(ah + 2 * j) = bfpack(x, y);
                *(uint32_t*)(al + 2 * j) = bfpack(rx, ry);
            }
        }
    } else {
        // --- fused GIN gather: z = (1+eps)*aff(h) + sum_in rh[src]; K must be 64 ---
        int gw = tid >> 5, lane = tid & 31;
        float ep = 1.f + epsArr[layer];
        float sx = 1.f, sy = 1.f, hx = 0.f, hy = 0.f;
        if (affineIdx >= 0) {
            float2 s2 = *(const float2*)(d_scE + affineIdx * HDIM + lane * 2);
            float2 h2 = *(const float2*)(d_shE + affineIdx * HDIM + lane * 2);
            sx = s2.x; sy = s2.y; hx = h2.x; hy = h2.y;
        }
        const __half2* rh = (const __half2*)d_rh;
        for (int t = 0; t < 16; t++) {
            int row = gw * 16 + t;
            int node = row0 + row;
            float zx = 0.f, zy = 0.f;
            if (node < n) {
                float ax0 = 0.f, ay0 = 0.f, ax1 = 0.f, ay1 = 0.f;
                float ax2 = 0.f, ay2 = 0.f, ax3 = 0.f, ay3 = 0.f;
                int start = d_off[node], cnt = d_deg[node];
                for (int base = 0; base < cnt; base += 32) {
                    int idx = 0;
                    if (base + lane < cnt) idx = d_csr[start + base + lane];
                    int m = min(32, cnt - base);
                    int j = 0;
                    for (; j + 4 <= m; j += 4) {
                        int s0 = __shfl_sync(0xffffffffu, idx, j);
                        int s1 = __shfl_sync(0xffffffffu, idx, j + 1);
                        int s2 = __shfl_sync(0xffffffffu, idx, j + 2);
                        int s3 = __shfl_sync(0xffffffffu, idx, j + 3);
                        float2 f0 = __half22float2(rh[s0 * (HDIM / 2) + lane]);
                        float2 f1 = __half22float2(rh[s1 * (HDIM / 2) + lane]);
                        float2 f2 = __half22float2(rh[s2 * (HDIM / 2) + lane]);
                        float2 f3 = __half22float2(rh[s3 * (HDIM / 2) + lane]);
                        ax0 += f0.x; ay0 += f0.y;
                        ax1 += f1.x; ay1 += f1.y;
                        ax2 += f2.x; ay2 += f2.y;
                        ax3 += f3.x; ay3 += f3.y;
                    }
                    for (; j < m; j++) {
                        int s = __shfl_sync(0xffffffffu, idx, j);
                        float2 f = __half22float2(rh[s * (HDIM / 2) + lane]);
                        ax0 += f.x; ay0 += f.y;
                    }
                }
                float ax = (ax0 + ax1) + (ax2 + ax3);
                float ay = (ay0 + ay1) + (ay2 + ay3);
                float2 c = *(const float2*)(d_h + (size_t)node * HDIM + lane * 2);
                zx = fmaf(ep, fmaf(sx, c.x, hx), ax);
                zy = fmaf(ep, fmaf(sy, c.y, hy), ay);
            }
            float rxx = zx - __bfloat162float(__float2bfloat16(zx));
            float ryy = zy - __bfloat162float(__float2bfloat16(zy));
            *(uint32_t*)(a_hi + row * LDIM + lane * 2) = bfpack(zx, zy);
            *(uint32_t*)(a_lo + row * LDIM + lane * 2) = bfpack(rxx, ryy);
        }
    }
    __syncthreads();

    int wid = tid >> 5, lane = tid & 31;
    int g = lane >> 2, tig = lane & 3;
    int wr = wid * 16;

    float acc[NT][4];
#pragma unroll
    for (int t = 0; t < NT; t++) {
        acc[t][0] = 0.f; acc[t][1] = 0.f; acc[t][2] = 0.f; acc[t][3] = 0.f;
    }

#pragma unroll
    for (int t = 0; t < 3; t++) {
        const __nv_bfloat16* As = (t == 1) ? a_lo : a_hi;
        const __nv_bfloat16* Bs = (t == 2) ? b_lo : b_hi;
        const __nv_bfloat16* ap = As + (wr + g) * LDIM + tig * 2;
        const __nv_bfloat16* bp = Bs + g * LDIM + tig * 2;
        for (int ks = 0; ks < K / 16; ks++) {
            int ko = ks * 16;
            uint32_t a0 = *(const uint32_t*)(ap + ko);
            uint32_t a1 = *(const uint32_t*)(ap + 8 * LDIM + ko);
            uint32_t a2 = *(const uint32_t*)(ap + ko + 8);
            uint32_t a3 = *(const uint32_t*)(ap + 8 * LDIM + ko + 8);
#pragma unroll
            for (int nt = 0; nt < NT; nt++) {
                uint32_t b0 = *(const uint32_t*)(bp + nt * 8 * LDIM + ko);
                uint32_t b1 = *(const uint32_t*)(bp + nt * 8 * LDIM + ko + 8);
                asm volatile(
                    "mma.sync.aligned.m16n8k16.row.col.f32.bf16.bf16.f32 "
                    "{%0,%1,%2,%3}, {%4,%5,%6,%7}, {%8,%9}, {%0,%1,%2,%3};"
                    : "+f"(acc[nt][0]), "+f"(acc[nt][1]), "+f"(acc[nt][2]), "+f"(acc[nt][3])
                    : "r"(a0), "r"(a1), "r"(a2), "r"(a3), "r"(b0), "r"(b1));
            }
        }
    }

    int r0 = row0 + wr + g;
    int r1 = r0 + 8;
    bool ok0 = r0 < n, ok1 = r1 < n;
#pragma unroll
    for (int nt = 0; nt < NT; nt++) {
        int cb = nt * 8 + tig * 2;
        float bb0 = bias[cb], bb1 = bias[cb + 1];
        float v00 = acc[nt][0] + bb0, v01 = acc[nt][1] + bb1;
        float v10 = acc[nt][2] + bb0, v11 = acc[nt][3] + bb1;
        if (ODST == 0) {
            if (ok0) *(float2*)(d_h + (size_t)r0 * N + cb) = make_float2(v00, v01);
            if (ok1) *(float2*)(d_h + (size_t)r1 * N + cb) = make_float2(v10, v11);
        } else {
            __half2* op = (__half2*)d_t;
            if (ok0) op[(size_t)r0 * (N / 2) + (cb >> 1)] = __floats2half2_rn(v00, v01);
            if (ok1) op[(size_t)r1 * (N / 2) + (cb >> 1)] = __floats2half2_rn(v10, v11);
        }
        if (N == HDIM && emit_rh) {
            __half2* rhp = (__half2*)d_rh;
            if (ok0) rhp[r0 * (HDIM / 2) + (cb >> 1)] =
                __floats2half2_rn(fmaxf(v00, 0.f), fmaxf(v01, 0.f));
            if (ok1) rhp[r1 * (HDIM / 2) + (cb >> 1)] =
                __floats2half2_rn(fmaxf(v10, 0.f), fmaxf(v11, 0.f));
        }
        if (STAT) {
            float s0 = (ok0 ? v00 : 0.f) + (ok1 ? v10 : 0.f);
            float s1 = (ok0 ? v01 : 0.f) + (ok1 ? v11 : 0.f);
            float q0 = (ok0 ? v00 * v00 : 0.f) + (ok1 ? v10 * v10 : 0.f);
            float q1 = (ok0 ? v01 * v01 : 0.f) + (ok1 ? v11 * v11 : 0.f);
#pragma unroll
            for (int o = 4; o <= 16; o <<= 1) {
                s0 += __shfl_xor_sync(0xffffffffu, s0, o);
                s1 += __shfl_xor_sync(0xffffffffu, s1, o);
                q0 += __shfl_xor_sync(0xffffffffu, q0, o);
                q1 += __shfl_xor_sync(0xffffffffu, q1, o);
            }
            if (lane < 4) {
                stS[wid * N + cb] = s0;
                stS[wid * N + cb + 1] = s1;
                stQ[wid * N + cb] = q0;
                stQ[wid * N + cb + 1] = q1;
            }
        }
    }
    if (STAT) {
        __syncthreads();
        if (tid < N) {
            float s = 0.f, q = 0.f;
#pragma unroll
            for (int w = 0; w < 8; w++) { s += stS[w * N + tid]; q += stQ[w * N + tid]; }
            float* sS = (STAT == 1) ? (d_statTS + layer * H2DIM) : (d_statHS + layer * HDIM);
            float* sQ = (STAT == 1) ? (d_statTQ + layer * H2DIM) : (d_statHQ + layer * HDIM);
            atomicAdd(sS + tid, s);
            atomicAdd(sQ + tid, q);
        }
    }
}

// ---------------- BN affine prep ----------------
__global__ void k_bnprep(const float* __restrict__ g, const float* __restrict__ be,
                         int mode, int layer, float invn) {
    int c = threadIdx.x;
    int cols = (mode == 0) ? H2DIM : HDIM;
    if (c >= cols) return;
    float S, Q;
    if (mode == 0) { S = d_statTS[layer * H2DIM + c]; Q = d_statTQ[layer * H2DIM + c]; }
    else           { S = d_statHS[layer * HDIM + c];  Q = d_statHQ[layer * HDIM + c]; }
    float mu = S * invn;
    float var = fmaf(-mu, mu, Q * invn);
    float sc = g[c] * rsqrtf(var + 1e-5f);
    float sh = fmaf(-mu, sc, be[c]);
    if (mode == 0) { d_sc1[c] = sc; d_sh1[c] = sh; }
    else { d_scE[(layer - 1) * HDIM + c] = sc; d_shE[(layer - 1) * HDIM + c] = sh; }
}

// ---------------- attention pooling ----------------
__global__ void k_gate(const float* __restrict__ gw, const float* __restrict__ gb,
                       const int* __restrict__ batch, int n) {
    __shared__ float sgt[8];
    __shared__ int sgr[8];
    int wid = threadIdx.x >> 5;
    int node = (blockIdx.x * blockDim.x + threadIdx.x) >> 5;
    int lane = threadIdx.x & 31;
    bool act = node < n;
    float gt = -3.4e38f;
    int g = -1;
    if (act) {
        float2 s2 = *(const float2*)(d_scE + HDIM + lane * 2);
        float2 h2 = *(const float2*)(d_shE + HDIM + lane * 2);
        float2 v = *(const float2*)(d_h + (size_t)node * HDIM + lane * 2);
        float w0 = gw[lane * 2], w1 = gw[lane * 2 + 1];
        float p = fmaf(s2.x, v.x, h2.x) * w0 + fmaf(s2.y, v.y, h2.y) * w1;
        for (int o = 16; o > 0; o >>= 1) p += __shfl_xor_sync(0xffffffffu, p, o);
        gt = p + gb[0];
        g = batch[node];
        if (lane == 0) d_gate[node] = gt;
    }
    if (lane == 0) { sgt[wid] = gt; sgr[wid] = act ? g : -1; }
    __syncthreads();
    if (threadIdx.x == 0) {
        int g0 = sgr[0];
        bool uni = true;
#pragma unroll
        for (int w = 1; w < 8; w++) uni &= (sgr[w] == g0 || sgr[w] == -1);
        if (uni && g0 >= 0) {
            float mx = sgt[0];
#pragma unroll
            for (int w = 1; w < 8; w++) if (sgr[w] >= 0) mx = fmaxf(mx, sgt[w]);
            unsigned u = __float_as_uint(mx);
            unsigned enc = (u & 0x80000000u) ? ~u : (u | 0x80000000u);
            atomicMax(&d_gmax[g0], enc);
        } else {
#pragma unroll
            for (int w = 0; w < 8; w++) {
                if (sgr[w] >= 0) {
                    unsigned u = __float_as_uint(sgt[w]);
                    unsigned enc = (u & 0x80000000u) ? ~u : (u | 0x80000000u);
                    atomicMax(&d_gmax[sgr[w]], enc);
                }
            }
        }
    }
}

__global__ void k_pool(const int* __restrict__ batch, int n) {
    __shared__ float sp[8][HDIM];
    __shared__ float sw[8];
    __shared__ int sgr[8];
    int wid = threadIdx.x >> 5;
    int node = (blockIdx.x * blockDim.x + threadIdx.x) >> 5;
    int lane = threadIdx.x & 31;
    bool act = node < n;
    int g = -1;
    float c0 = 0.f, c1 = 0.f, w = 0.f;
    if (act) {
        g = batch[node];
        unsigned encm = d_gmax[g];
        float gmax = (encm & 0x80000000u) ? __uint_as_float(encm & 0x7fffffffu)
                                          : __uint_as_float(~encm);
        w = expf(d_gate[node] - gmax);
        float2 s2 = *(const float2*)(d_scE + HDIM + lane * 2);
        float2 h2 = *(const float2*)(d_shE + HDIM + lane * 2);
        float2 v = *(const float2*)(d_h + (size_t)node * HDIM + lane * 2);
        c0 = w * fmaf(s2.x, v.x, h2.x);
        c1 = w * fmaf(s2.y, v.y, h2.y);
    }
    sp[wid][lane * 2] = c0;
    sp[wid][lane * 2 + 1] = c1;
    if (lane == 0) { sw[wid] = act ? w : 0.f; sgr[wid] = act ? g : -1; }
    __syncthreads();
    int g0 = sgr[0];
    bool uni = true;
#pragma unroll
    for (int ww = 1; ww < 8; ww++) uni &= (sgr[ww] == g0 || sgr[ww] == -1);
    if (uni && g0 >= 0) {
        if (wid == 0) {
            float a0 = 0.f, a1 = 0.f;
#pragma unroll
            for (int ww = 0; ww < 8; ww++) {
                a0 += sp[ww][lane * 2];
                a1 += sp[ww][lane * 2 + 1];
            }
            atomicAdd(&d_poolS[g0 * HDIM + lane * 2], a0);
            atomicAdd(&d_poolS[g0 * HDIM + lane * 2 + 1], a1);
            if (lane == 0) {
                float ws = 0.f;
#pragma unroll
                for (int ww = 0; ww < 8; ww++) ws += sw[ww];
                atomicAdd(&d_wsum[g0], ws);
            }
        }
    } else if (act) {
        atomicAdd(&d_poolS[g * HDIM + lane * 2], c0);
        atomicAdd(&d_poolS[g * HDIM + lane * 2 + 1], c1);
        if (lane == 0) atomicAdd(&d_wsum[g], w);
    }
}

__global__ void k_final(const float* __restrict__ pW, const float* __restrict__ pb,
                        const float* __restrict__ cW, const float* __restrict__ cb,
                        float* __restrict__ out, int G) {
    int g = blockIdx.x * blockDim.x + threadIdx.x;
    if (g >= G) return;
    float inv = 1.f / d_wsum[g];
    float pooled[HDIM];
#pragma unroll
    for (int f = 0; f < HDIM; f++) pooled[f] = d_poolS[g * HDIM + f] * inv;
    float z[HDIM];
    for (int o = 0; o < HDIM; o++) {
        float a = pb[o];
        for (int i2 = 0; i2 < HDIM; i2++) a = fmaf(pooled[i2], pW[i2 * HDIM + o], a);
        z[o] = fmaxf(a, 0.f);
    }
    for (int c = 0; c < 2; c++) {
        float a = cb[c];
        for (int i2 = 0; i2 < HDIM; i2++) a = fmaf(z[i2], cW[i2 * 2 + c], a);
        out[g * 2 + c] = a;
    }
}

// ---------------- launch ----------------
extern "C" void kernel_launch(void* const* d_in, const int* in_sizes, int n_in,
                              void* d_out, int out_size) {
    const float* x     = (const float*)d_in[0];
    const float* l0W   = (const float*)d_in[1];
    const float* l0b   = (const float*)d_in[2];
    const float* eps   = (const float*)d_in[3];
    const float* W1    = (const float*)d_in[4];
    const float* b1    = (const float*)d_in[5];
    const float* g1    = (const float*)d_in[6];
    const float* be1   = (const float*)d_in[7];
    const float* W2    = (const float*)d_in[8];
    const float* b2    = (const float*)d_in[9];
    const float* gbn   = (const float*)d_in[10];
    const float* bbn   = (const float*)d_in[11];
    const float* gateW = (const float*)d_in[12];
    const float* gateb = (const float*)d_in[13];
    const float* predW = (const float*)d_in[14];
    const float* predb = (const float*)d_in[15];
    const float* clsW  = (const float*)d_in[16];
    const float* clsb  = (const float*)d_in[17];
    const int*   eidx  = (const int*)d_in[18];
    const int*   batch = (const int*)d_in[19];

    int n = in_sizes[0] / FDIM; if (n > MAXN) n = MAXN;
    int e = in_sizes[18] / 2;   if (e > MAXE) e = MAXE;
    int G = out_size / 2;       if (G > MAXG) G = MAXG;
    const int* src  = eidx;
    const int* dstp = eidx + e;
    float invn = 1.0f / (float)n;

    const int SM_K128N64 = 2 * (128 * 136 * 2) + 2 * (64 * 136 * 2) + 16 * 64 * 4;   // 108544
    const int SM_K64N128 = 2 * (128 * 72 * 2) + 2 * (128 * 72 * 2) + 16 * 128 * 4;   // 81920
    cudaFuncSetAttribute(k_gemm_mma<128, 64, 0, 0, false, 0>,
                         cudaFuncAttributeMaxDynamicSharedMemorySize, SM_K128N64);
    cudaFuncSetAttribute(k_gemm_mma<64, 128, 3, 1, false, 1>,
                         cudaFuncAttributeMaxDynamicSharedMemorySize, SM_K64N128);
    cudaFuncSetAttribute(k_gemm_mma<128, 64, 2, 0, true, 2>,
                         cudaFuncAttributeMaxDynamicSharedMemorySize, SM_K128N64);

    k_init<<<256, 256>>>(n, G);
    int eb = (e + 255) / 256;
    k_hist<<<eb, 256>>>(dstp, e);
    int nb = (n + 1023) / 1024;
    k_scan1<<<nb, 1024>>>(n);
    k_scan2<<<1, 128>>>(nb);
    k_scan3<<<(n + 255) / 256, 256>>>(n);
    k_scatter<<<eb, 256>>>(src, dstp, e);

    int gb = (n + GROWS - 1) / GROWS;
    // lin0 output feeds gather(0): emit fp16 relu copy in epilogue
    k_gemm_mma<128, 64, 0, 0, false, 0><<<gb, 256, SM_K128N64>>>(
        x, l0W, l0b, 0, n, 1, eps, -1);

    int pb2 = (n * (HDIM / 2) + 255) / 256;
    for (int i = 0; i < 3; i++) {
        int aff = (i == 2) ? 0 : -1;   // conv3 input = extBN(gbn[0]) of conv2 output
        if (i == 2) k_prep<<<pb2, 256>>>(0, n);   // rebuild rh with extBN affine
        // fused gather + GEMM1 (z never hits gmem)
        k_gemm_mma<64, 128, 3, 1, false, 1><<<gb, 256, SM_K64N128>>>(
            nullptr, W1 + i * HDIM * H2DIM, b1 + i * H2DIM, i, n, 0, eps, aff);
        k_bnprep<<<1, 128>>>(g1 + i * H2DIM, be1 + i * H2DIM, 0, i, invn);
        k_gemm_mma<128, 64, 2, 0, true, 2><<<gb, 256, SM_K128N64>>>(
            nullptr, W2 + i * H2DIM * HDIM, b2 + i * HDIM, i, n, (i == 0) ? 1 : 0, eps, -1);
        if (i >= 1)
            k_bnprep<<<1, 128>>>(gbn + (i - 1) * HDIM, bbn + (i - 1) * HDIM, 1, i, invn);
    }

    k_gate<<<(n * 32 + 255) / 256, 256>>>(gateW, gateb, batch, n);
    k_pool<<<(n * 32 + 255) / 256, 256>>>(batch, n);
    k_final<<<(G + 127) / 128, 128>>>(predW, predb, clsW, clsb, (float*)d_out, G);
}

// round 9
// speedup vs baseline: 1.2397x; 1.2397x over previous
#include <cuda_runtime.h>
#include <cuda_bf16.h>
#include <cuda_fp16.h>
#include <cstdint>

#define MAXN 100000
#define MAXE 3200000
#define FDIM 128
#define HDIM 64
#define H2DIM 128
#define MAXG 256
#define GROWS 128   // rows per GEMM block tile

// ---------------- device scratch (static, no allocation) ----------------
__device__ __align__(16) float d_h[(size_t)MAXN * HDIM];
__device__ __align__(16) float d_z[(size_t)MAXN * HDIM];
__device__ __align__(16) __half d_t[(size_t)MAXN * H2DIM];   // fp16 intermediate
__device__ __align__(16) __half d_rh[(size_t)MAXN * HDIM];   // relu(aff(h)) as fp16
__device__ int   d_deg[MAXN];
__device__ int   d_off[MAXN];
__device__ int   d_cur[MAXN];
__device__ int   d_csr[MAXE];
__device__ int   d_bsum[256];
__device__ int   d_boff[256];
__device__ __align__(16) float d_statTS[3 * H2DIM];
__device__ __align__(16) float d_statTQ[3 * H2DIM];
__device__ __align__(16) float d_statHS[3 * HDIM];
__device__ __align__(16) float d_statHQ[3 * HDIM];
__device__ __align__(16) float d_sc1[H2DIM];
__device__ __align__(16) float d_sh1[H2DIM];
__device__ __align__(16) float d_scE[2 * HDIM];
__device__ __align__(16) float d_shE[2 * HDIM];
__device__ unsigned d_gmax[MAXG];
__device__ float d_wsum[MAXG];
__device__ __align__(16) float d_poolS[MAXG * HDIM];
__device__ float d_gate[MAXN];

// ---------------- init ----------------
__global__ void k_init(int n, int G) {
    int stride = gridDim.x * blockDim.x;
    int i0 = blockIdx.x * blockDim.x + threadIdx.x;
    for (int i = i0; i < n; i += stride) d_deg[i] = 0;
    for (int i = i0; i < 3 * H2DIM; i += stride) { d_statTS[i] = 0.f; d_statTQ[i] = 0.f; }
    for (int i = i0; i < 3 * HDIM; i += stride) { d_statHS[i] = 0.f; d_statHQ[i] = 0.f; }
    for (int i = i0; i < G; i += stride) { d_gmax[i] = 0u; d_wsum[i] = 0.f; }
    for (int i = i0; i < G * HDIM; i += stride) d_poolS[i] = 0.f;
}

// ---------------- CSR build ----------------
__global__ void k_hist(const int* __restrict__ dst, int e) {
    int i = blockIdx.x * blockDim.x + threadIdx.x;
    if (i < e) atomicAdd(&d_deg[dst[i]], 1);
}

__global__ void k_scan1(int n) {
    __shared__ int s[1024];
    int i = blockIdx.x * 1024 + threadIdx.x;
    int v = (i < n) ? d_deg[i] : 0;
    s[threadIdx.x] = v;
    __syncthreads();
    for (int d = 1; d < 1024; d <<= 1) {
        int t = 0;
        if ((int)threadIdx.x >= d) t = s[threadIdx.x - d];
        __syncthreads();
        s[threadIdx.x] += t;
        __syncthreads();
    }
    if (i < n) d_off[i] = s[threadIdx.x] - v;
    if (threadIdx.x == 1023) d_bsum[blockIdx.x] = s[1023];
}

__global__ void k_scan2(int nb) {
    int t = threadIdx.x;
    int v = (t < nb) ? d_bsum[t] : 0;
    int orig = v;
    for (int d = 1; d < 32; d <<= 1) {
        int u = __shfl_up_sync(0xffffffffu, v, d);
        if ((t & 31) >= d) v += u;
    }
    __shared__ int ws[4];
    if ((t & 31) == 31) ws[t >> 5] = v;
    __syncthreads();
    int add = 0;
    for (int w = 0; w < (t >> 5); w++) add += ws[w];
    if (t < nb) d_boff[t] = v + add - orig;
}

__global__ void k_scan3(int n) {
    int i = blockIdx.x * blockDim.x + threadIdx.x;
    if (i < n) {
        int v = d_off[i] + d_boff[i >> 10];
        d_off[i] = v;
        d_cur[i] = v;
    }
}

__global__ void k_scatter(const int* __restrict__ src, const int* __restrict__ dst, int e) {
    int i = blockIdx.x * blockDim.x + threadIdx.x;
    if (i < e) {
        int d = dst[i];
        int p = atomicAdd(&d_cur[d], 1);
        d_csr[p] = src[i];
    }
}

// ---------------- prep: d_rh = fp16(relu(scE[idx]*h + shE[idx])) ----------------
__global__ void k_prep(int affineIdx, int n) {
    int i = blockIdx.x * blockDim.x + threadIdx.x;
    if (i >= n * (HDIM / 2)) return;
    int c = i & (HDIM / 2 - 1);
    float2 v = ((const float2*)d_h)[i];
    float2 s2 = *(const float2*)(d_scE + affineIdx * HDIM + c * 2);
    float2 h2 = *(const float2*)(d_shE + affineIdx * HDIM + c * 2);
    float rx = fmaxf(fmaf(s2.x, v.x, h2.x), 0.f);
    float ry = fmaxf(fmaf(s2.y, v.y, h2.y), 0.f);
    ((__half2*)d_rh)[i] = __floats2half2_rn(rx, ry);
}

// ---------------- gather: z = (1+eps)*aff(h) + sum_in rh[src] ----------------
// Half-warp per node: 16 lanes x uint2 (4 halfs) = 128B row per edge, 2 nodes/warp.
__global__ void k_gather(const float* __restrict__ epsArr, int layer, int affineIdx, int n) {
    int warp = (blockIdx.x * blockDim.x + threadIdx.x) >> 5;
    int lane = threadIdx.x & 31;
    int grp = lane >> 4, li = lane & 15;
    int node = warp * 2 + grp;
    if (node >= n) return;
    unsigned mask = 0xFFFFu << (grp * 16);
    const uint2* rh = (const uint2*)d_rh;   // row stride = 16 uint2 (64 halfs)
    float a0 = 0.f, a1 = 0.f, a2 = 0.f, a3 = 0.f;   // channels li*4..li*4+3 (s0 stream)
    float b0 = 0.f, b1 = 0.f, b2 = 0.f, b3 = 0.f;   // s1 stream
    int start = d_off[node], cnt = d_deg[node];
    for (int base = 0; base < cnt; base += 16) {
        int idx = 0;
        if (base + li < cnt) idx = d_csr[start + base + li];
        int m = min(16, cnt - base);
        int j = 0;
        for (; j + 2 <= m; j += 2) {
            int s0 = __shfl_sync(mask, idx, grp * 16 + j);
            int s1 = __shfl_sync(mask, idx, grp * 16 + j + 1);
            uint2 r0 = rh[s0 * 16 + li];
            uint2 r1 = rh[s1 * 16 + li];
            float2 f0 = __half22float2(*(__half2*)&r0.x);
            float2 f1 = __half22float2(*(__half2*)&r0.y);
            float2 g0 = __half22float2(*(__half2*)&r1.x);
            float2 g1 = __half22float2(*(__half2*)&r1.y);
            a0 += f0.x; a1 += f0.y; a2 += f1.x; a3 += f1.y;
            b0 += g0.x; b1 += g0.y; b2 += g1.x; b3 += g1.y;
        }
        for (; j < m; j++) {
            int s = __shfl_sync(mask, idx, grp * 16 + j);
            uint2 r0 = rh[s * 16 + li];
            float2 f0 = __half22float2(*(__half2*)&r0.x);
            float2 f1 = __half22float2(*(__half2*)&r0.y);
            a0 += f0.x; a1 += f0.y; a2 += f1.x; a3 += f1.y;
        }
    }
    a0 += b0; a1 += b1; a2 += b2; a3 += b3;
    float4 sc = make_float4(1.f, 1.f, 1.f, 1.f);
    float4 sh = make_float4(0.f, 0.f, 0.f, 0.f);
    if (affineIdx >= 0) {
        sc = *(const float4*)(d_scE + affineIdx * HDIM + li * 4);
        sh = *(const float4*)(d_shE + affineIdx * HDIM + li * 4);
    }
    float ep = 1.f + epsArr[layer];
    float4 c = *(const float4*)(d_h + (size_t)node * HDIM + li * 4);
    float4 z;
    z.x = fmaf(ep, fmaf(sc.x, c.x, sh.x), a0);
    z.y = fmaf(ep, fmaf(sc.y, c.y, sh.y), a1);
    z.z = fmaf(ep, fmaf(sc.z, c.z, sh.z), a2);
    z.w = fmaf(ep, fmaf(sc.w, c.w, sh.w), a3);
    *(float4*)(d_z + (size_t)node * HDIM + li * 4) = z;
}

// ---------------- HMMA GEMM: out[n,N] = act(A[n,K]) @ W[K,N] + bias ----------------
// 3-term bf16 split: D = Ahi@Bhi + Alo@Bhi + Ahi@Blo, fp32 accum (mma.sync m16n8k16).
// ASRC: 0=Apar fp32, 1=d_z fp32, 2=d_t fp16 (+TRANS)   ODST: 0=d_h fp32, 1=d_t fp16
// STAT: 0 none, 1 statT, 2 statH.  emit_rh: write d_rh=fp16(relu(out)) (N=64 only).
__device__ __forceinline__ uint32_t bfpack(float x, float y) {
    __nv_bfloat16 bx = __float2bfloat16(x), by = __float2bfloat16(y);
    return ((uint32_t)__bfloat16_as_ushort(by) << 16) | __bfloat16_as_ushort(bx);
}

template <int K, int N, int ASRC, int ODST, bool TRANS, int STAT>
__global__ void __launch_bounds__(256)
k_gemm_mma(const float* __restrict__ Apar, const float* __restrict__ W,
           const float* __restrict__ bias, int layer, int n, int emit_rh) {
    constexpr int NT = N / 8;
    constexpr int LDIM = K + 8;
    constexpr int ASZ = GROWS * LDIM * 2;
    constexpr int BSZ = N * LDIM * 2;
    extern __shared__ __align__(16) char smem[];
    __nv_bfloat16* a_hi = (__nv_bfloat16*)(smem);
    __nv_bfloat16* a_lo = (__nv_bfloat16*)(smem + ASZ);
    __nv_bfloat16* b_hi = (__nv_bfloat16*)(smem + 2 * ASZ);
    __nv_bfloat16* b_lo = (__nv_bfloat16*)(smem + 2 * ASZ + BSZ);
    float* stS = (float*)(smem + 2 * ASZ + 2 * BSZ);   // [8][N]
    float* stQ = stS + 8 * N;

    int tid = threadIdx.x;
    int row0 = blockIdx.x * GROWS;

    for (int idx = tid; idx < K * N; idx += 256) {
        int k = idx / N, nn = idx - k * N;
        float v = W[idx];
        __nv_bfloat16 h = __float2bfloat16(v);
        __nv_bfloat16 l = __float2bfloat16(v - __bfloat162float(h));
        b_hi[nn * LDIM + k] = h;
        b_lo[nn * LDIM + k] = l;
    }

    // --- A tile: coalesced linear load ---
    if (ASRC != 2) {
        const float* A = (ASRC == 0) ? Apar : d_z;
        for (int idx = tid; idx < GROWS * K / 4; idx += 256) {
            int row = idx / (K / 4);
            int kf = (idx - row * (K / 4)) * 4;
            int grow = row0 + row;
            float4 v = make_float4(0.f, 0.f, 0.f, 0.f);
            if (grow < n) v = *(const float4*)(A + (size_t)grow * K + kf);
            float rx = v.x - __bfloat162float(__float2bfloat16(v.x));
            float ry = v.y - __bfloat162float(__float2bfloat16(v.y));
            float rz = v.z - __bfloat162float(__float2bfloat16(v.z));
            float rw = v.w - __bfloat162float(__float2bfloat16(v.w));
            __nv_bfloat16* ah = a_hi + row * LDIM + kf;
            __nv_bfloat16* al = a_lo + row * LDIM + kf;
            *(uint32_t*)(ah) = bfpack(v.x, v.y);
            *(uint32_t*)(ah + 2) = bfpack(v.z, v.w);
            *(uint32_t*)(al) = bfpack(rx, ry);
            *(uint32_t*)(al + 2) = bfpack(rz, rw);
        }
    } else {
        const __half* A = d_t;
        for (int idx = tid; idx < GROWS * K / 8; idx += 256) {
            int row = idx / (K / 8);
            int kf = (idx - row * (K / 8)) * 8;
            int grow = row0 + row;
            uint4 raw = make_uint4(0u, 0u, 0u, 0u);
            if (grow < n) raw = *(const uint4*)(A + (size_t)grow * K + kf);
            float v[8];
            {
                float2 p0 = __half22float2(*(__half2*)&raw.x);
                float2 p1 = __half22float2(*(__half2*)&raw.y);
                float2 p2 = __half22float2(*(__half2*)&raw.z);
                float2 p3 = __half22float2(*(__half2*)&raw.w);
                v[0] = p0.x; v[1] = p0.y; v[2] = p1.x; v[3] = p1.y;
                v[4] = p2.x; v[5] = p2.y; v[6] = p3.x; v[7] = p3.y;
            }
            if (TRANS) {
#pragma unroll
                for (int j = 0; j < 8; j++)
                    v[j] = fmaxf(fmaf(d_sc1[kf + j], v[j], d_sh1[kf + j]), 0.f);
            }
            __nv_bfloat16* ah = a_hi + row * LDIM + kf;
            __nv_bfloat16* al = a_lo + row * LDIM + kf;
#pragma unroll
            for (int j = 0; j < 4; j++) {
                float x = v[2 * j], y = v[2 * j + 1];
                float rx = x - __bfloat162float(__float2bfloat16(x));
                float ry = y - __bfloat162float(__float2bfloat16(y));
                *(uint32_t*)(ah + 2 * j) = bfpack(x, y);
                *(uint32_t*)(al + 2 * j) = bfpack(rx, ry);
            }
        }
    }
    __syncthreads();

    int wid = tid >> 5, lane = tid & 31;
    int g = lane >> 2, tig = lane & 3;
    int wr = wid * 16;

    float acc[NT][4];
#pragma unroll
    for (int t = 0; t < NT; t++) {
        acc[t][0] = 0.f; acc[t][1] = 0.f; acc[t][2] = 0.f; acc[t][3] = 0.f;
    }

#pragma unroll
    for (int t = 0; t < 3; t++) {
        const __nv_bfloat16* As = (t == 1) ? a_lo : a_hi;
        const __nv_bfloat16* Bs = (t == 2) ? b_lo : b_hi;
        const __nv_bfloat16* ap = As + (wr + g) * LDIM + tig * 2;
        const __nv_bfloat16* bp = Bs + g * LDIM + tig * 2;
        for (int ks = 0; ks < K / 16; ks++) {
            int ko = ks * 16;
            uint32_t a0 = *(const uint32_t*)(ap + ko);
            uint32_t a1 = *(const uint32_t*)(ap + 8 * LDIM + ko);
            uint32_t a2 = *(const uint32_t*)(ap + ko + 8);
            uint32_t a3 = *(const uint32_t*)(ap + 8 * LDIM + ko + 8);
#pragma unroll
            for (int nt = 0; nt < NT; nt++) {
                uint32_t b0 = *(const uint32_t*)(bp + nt * 8 * LDIM + ko);
                uint32_t b1 = *(const uint32_t*)(bp + nt * 8 * LDIM + ko + 8);
                asm volatile(
                    "mma.sync.aligned.m16n8k16.row.col.f32.bf16.bf16.f32 "
                    "{%0,%1,%2,%3}, {%4,%5,%6,%7}, {%8,%9}, {%0,%1,%2,%3};"
                    : "+f"(acc[nt][0]), "+f"(acc[nt][1]), "+f"(acc[nt][2]), "+f"(acc[nt][3])
                    : "r"(a0), "r"(a1), "r"(a2), "r"(a3), "r"(b0), "r"(b1));
            }
        }
    }

    int r0 = row0 + wr + g;
    int r1 = r0 + 8;
    bool ok0 = r0 < n, ok1 = r1 < n;
#pragma unroll
    for (int nt = 0; nt < NT; nt++) {
        int cb = nt * 8 + tig * 2;
        float bb0 = bias[cb], bb1 = bias[cb + 1];
        float v00 = acc[nt][0] + bb0, v01 = acc[nt][1] + bb1;
        float v10 = acc[nt][2] + bb0, v11 = acc[nt][3] + bb1;
        if (ODST == 0) {
            if (ok0) *(float2*)(d_h + (size_t)r0 * N + cb) = make_float2(v00, v01);
            if (ok1) *(float2*)(d_h + (size_t)r1 * N + cb) = make_float2(v10, v11);
        } else {
            __half2* op = (__half2*)d_t;
            if (ok0) op[(size_t)r0 * (N / 2) + (cb >> 1)] = __floats2half2_rn(v00, v01);
            if (ok1) op[(size_t)r1 * (N / 2) + (cb >> 1)] = __floats2half2_rn(v10, v11);
        }
        if (N == HDIM && emit_rh) {
            __half2* rhp = (__half2*)d_rh;
            if (ok0) rhp[r0 * (HDIM / 2) + (cb >> 1)] =
                __floats2half2_rn(fmaxf(v00, 0.f), fmaxf(v01, 0.f));
            if (ok1) rhp[r1 * (HDIM / 2) + (cb >> 1)] =
                __floats2half2_rn(fmaxf(v10, 0.f), fmaxf(v11, 0.f));
        }
        if (STAT) {
            float s0 = (ok0 ? v00 : 0.f) + (ok1 ? v10 : 0.f);
            float s1 = (ok0 ? v01 : 0.f) + (ok1 ? v11 : 0.f);
            float q0 = (ok0 ? v00 * v00 : 0.f) + (ok1 ? v10 * v10 : 0.f);
            float q1 = (ok0 ? v01 * v01 : 0.f) + (ok1 ? v11 * v11 : 0.f);
#pragma unroll
            for (int o = 4; o <= 16; o <<= 1) {
                s0 += __shfl_xor_sync(0xffffffffu, s0, o);
                s1 += __shfl_xor_sync(0xffffffffu, s1, o);
                q0 += __shfl_xor_sync(0xffffffffu, q0, o);
                q1 += __shfl_xor_sync(0xffffffffu, q1, o);
            }
            if (lane < 4) {
                stS[wid * N + cb] = s0;
                stS[wid * N + cb + 1] = s1;
                stQ[wid * N + cb] = q0;
                stQ[wid * N + cb + 1] = q1;
            }
        }
    }
    if (STAT) {
        __syncthreads();
        if (tid < N) {
            float s = 0.f, q = 0.f;
#pragma unroll
            for (int w = 0; w < 8; w++) { s += stS[w * N + tid]; q += stQ[w * N + tid]; }
            float* sS = (STAT == 1) ? (d_statTS + layer * H2DIM) : (d_statHS + layer * HDIM);
            float* sQ = (STAT == 1) ? (d_statTQ + layer * H2DIM) : (d_statHQ + layer * HDIM);
            atomicAdd(sS + tid, s);
            atomicAdd(sQ + tid, q);
        }
    }
}

// ---------------- BN affine prep ----------------
__global__ void k_bnprep(const float* __restrict__ g, const float* __restrict__ be,
                         int mode, int layer, float invn) {
    int c = threadIdx.x;
    int cols = (mode == 0) ? H2DIM : HDIM;
    if (c >= cols) return;
    float S, Q;
    if (mode == 0) { S = d_statTS[layer * H2DIM + c]; Q = d_statTQ[layer * H2DIM + c]; }
    else           { S = d_statHS[layer * HDIM + c];  Q = d_statHQ[layer * HDIM + c]; }
    float mu = S * invn;
    float var = fmaf(-mu, mu, Q * invn);
    float sc = g[c] * rsqrtf(var + 1e-5f);
    float sh = fmaf(-mu, sc, be[c]);
    if (mode == 0) { d_sc1[c] = sc; d_sh1[c] = sh; }
    else { d_scE[(layer - 1) * HDIM + c] = sc; d_shE[(layer - 1) * HDIM + c] = sh; }
}

// ---------------- attention pooling ----------------
__global__ void k_gate(const float* __restrict__ gw, const float* __restrict__ gb,
                       const int* __restrict__ batch, int n) {
    __shared__ float sgt[8];
    __shared__ int sgr[8];
    int wid = threadIdx.x >> 5;
    int node = (blockIdx.x * blockDim.x + threadIdx.x) >> 5;
    int lane = threadIdx.x & 31;
    bool act = node < n;
    float gt = -3.4e38f;
    int g = -1;
    if (act) {
        float2 s2 = *(const float2*)(d_scE + HDIM + lane * 2);
        float2 h2 = *(const float2*)(d_shE + HDIM + lane * 2);
        float2 v = *(const float2*)(d_h + (size_t)node * HDIM + lane * 2);
        float w0 = gw[lane * 2], w1 = gw[lane * 2 + 1];
        float p = fmaf(s2.x, v.x, h2.x) * w0 + fmaf(s2.y, v.y, h2.y) * w1;
        for (int o = 16; o > 0; o >>= 1) p += __shfl_xor_sync(0xffffffffu, p, o);
        gt = p + gb[0];
        g = batch[node];
        if (lane == 0) d_gate[node] = gt;
    }
    if (lane == 0) { sgt[wid] = gt; sgr[wid] = act ? g : -1; }
    __syncthreads();
    if (threadIdx.x == 0) {
        int g0 = sgr[0];
        bool uni = true;
#pragma unroll
        for (int w = 1; w < 8; w++) uni &= (sgr[w] == g0 || sgr[w] == -1);
        if (uni && g0 >= 0) {
            float mx = sgt[0];
#pragma unroll
            for (int w = 1; w < 8; w++) if (sgr[w] >= 0) mx = fmaxf(mx, sgt[w]);
            unsigned u = __float_as_uint(mx);
            unsigned enc = (u & 0x80000000u) ? ~u : (u | 0x80000000u);
            atomicMax(&d_gmax[g0], enc);
        } else {
#pragma unroll
            for (int w = 0; w < 8; w++) {
                if (sgr[w] >= 0) {
                    unsigned u = __float_as_uint(sgt[w]);
                    unsigned enc = (u & 0x80000000u) ? ~u : (u | 0x80000000u);
                    atomicMax(&d_gmax[sgr[w]], enc);
                }
            }
        }
    }
}

__global__ void k_pool(const int* __restrict__ batch, int n) {
    __shared__ float sp[8][HDIM];
    __shared__ float sw[8];
    __shared__ int sgr[8];
    int wid = threadIdx.x >> 5;
    int node = (blockIdx.x * blockDim.x + threadIdx.x) >> 5;
    int lane = threadIdx.x & 31;
    bool act = node < n;
    int g = -1;
    float c0 = 0.f, c1 = 0.f, w = 0.f;
    if (act) {
        g = batch[node];
        unsigned encm = d_gmax[g];
        float gmax = (encm & 0x80000000u) ? __uint_as_float(encm & 0x7fffffffu)
                                          : __uint_as_float(~encm);
        w = expf(d_gate[node] - gmax);
        float2 s2 = *(const float2*)(d_scE + HDIM + lane * 2);
        float2 h2 = *(const float2*)(d_shE + HDIM + lane * 2);
        float2 v = *(const float2*)(d_h + (size_t)node * HDIM + lane * 2);
        c0 = w * fmaf(s2.x, v.x, h2.x);
        c1 = w * fmaf(s2.y, v.y, h2.y);
    }
    sp[wid][lane * 2] = c0;
    sp[wid][lane * 2 + 1] = c1;
    if (lane == 0) { sw[wid] = act ? w : 0.f; sgr[wid] = act ? g : -1; }
    __syncthreads();
    int g0 = sgr[0];
    bool uni = true;
#pragma unroll
    for (int ww = 1; ww < 8; ww++) uni &= (sgr[ww] == g0 || sgr[ww] == -1);
    if (uni && g0 >= 0) {
        if (wid == 0) {
            float a0 = 0.f, a1 = 0.f;
#pragma unroll
            for (int ww = 0; ww < 8; ww++) {
                a0 += sp[ww][lane * 2];
                a1 += sp[ww][lane * 2 + 1];
            }
            atomicAdd(&d_poolS[g0 * HDIM + lane * 2], a0);
            atomicAdd(&d_poolS[g0 * HDIM + lane * 2 + 1], a1);
            if (lane == 0) {
                float ws = 0.f;
#pragma unroll
                for (int ww = 0; ww < 8; ww++) ws += sw[ww];
                atomicAdd(&d_wsum[g0], ws);
            }
        }
    } else if (act) {
        atomicAdd(&d_poolS[g * HDIM + lane * 2], c0);
        atomicAdd(&d_poolS[g * HDIM + lane * 2 + 1], c1);
        if (lane == 0) atomicAdd(&d_wsum[g], w);
    }
}

__global__ void k_final(const float* __restrict__ pW, const float* __restrict__ pb,
                        const float* __restrict__ cW, const float* __restrict__ cb,
                        float* __restrict__ out, int G) {
    int g = blockIdx.x * blockDim.x + threadIdx.x;
    if (g >= G) return;
    float inv = 1.f / d_wsum[g];
    float pooled[HDIM];
#pragma unroll
    for (int f = 0; f < HDIM; f++) pooled[f] = d_poolS[g * HDIM + f] * inv;
    float z[HDIM];
    for (int o = 0; o < HDIM; o++) {
        float a = pb[o];
        for (int i2 = 0; i2 < HDIM; i2++) a = fmaf(pooled[i2], pW[i2 * HDIM + o], a);
        z[o] = fmaxf(a, 0.f);
    }
    for (int c = 0; c < 2; c++) {
        float a = cb[c];
        for (int i2 = 0; i2 < HDIM; i2++) a = fmaf(z[i2], cW[i2 * 2 + c], a);
        out[g * 2 + c] = a;
    }
}

// ---------------- launch ----------------
extern "C" void kernel_launch(void* const* d_in, const int* in_sizes, int n_in,
                              void* d_out, int out_size) {
    const float* x     = (const float*)d_in[0];
    const float* l0W   = (const float*)d_in[1];
    const float* l0b   = (const float*)d_in[2];
    const float* eps   = (const float*)d_in[3];
    const float* W1    = (const float*)d_in[4];
    const float* b1    = (const float*)d_in[5];
    const float* g1    = (const float*)d_in[6];
    const float* be1   = (const float*)d_in[7];
    const float* W2    = (const float*)d_in[8];
    const float* b2    = (const float*)d_in[9];
    const float* gbn   = (const float*)d_in[10];
    const float* bbn   = (const float*)d_in[11];
    const float* gateW = (const float*)d_in[12];
    const float* gateb = (const float*)d_in[13];
    const float* predW = (const float*)d_in[14];
    const float* predb = (const float*)d_in[15];
    const float* clsW  = (const float*)d_in[16];
    const float* clsb  = (const float*)d_in[17];
    const int*   eidx  = (const int*)d_in[18];
    const int*   batch = (const int*)d_in[19];

    int n = in_sizes[0] / FDIM; if (n > MAXN) n = MAXN;
    int e = in_sizes[18] / 2;   if (e > MAXE) e = MAXE;
    int G = out_size / 2;       if (G > MAXG) G = MAXG;
    const int* src  = eidx;
    const int* dstp = eidx + e;
    float invn = 1.0f / (float)n;

    const int SM_K128N64 = 2 * (128 * 136 * 2) + 2 * (64 * 136 * 2) + 16 * 64 * 4;   // 108544
    const int SM_K64N128 = 2 * (128 * 72 * 2) + 2 * (128 * 72 * 2) + 16 * 128 * 4;   // 81920
    cudaFuncSetAttribute(k_gemm_mma<128, 64, 0, 0, false, 0>,
                         cudaFuncAttributeMaxDynamicSharedMemorySize, SM_K128N64);
    cudaFuncSetAttribute(k_gemm_mma<64, 128, 1, 1, false, 1>,
                         cudaFuncAttributeMaxDynamicSharedMemorySize, SM_K64N128);
    cudaFuncSetAttribute(k_gemm_mma<128, 64, 2, 0, true, 2>,
                         cudaFuncAttributeMaxDynamicSharedMemorySize, SM_K128N64);

    k_init<<<256, 256>>>(n, G);
    int eb = (e + 255) / 256;
    k_hist<<<eb, 256>>>(dstp, e);
    int nb = (n + 1023) / 1024;
    k_scan1<<<nb, 1024>>>(n);
    k_scan2<<<1, 128>>>(nb);
    k_scan3<<<(n + 255) / 256, 256>>>(n);
    k_scatter<<<eb, 256>>>(src, dstp, e);

    int gb = (n + GROWS - 1) / GROWS;
    // lin0 output feeds gather(0): emit fp16 relu copy in epilogue
    k_gemm_mma<128, 64, 0, 0, false, 0><<<gb, 256, SM_K128N64>>>(x, l0W, l0b, 0, n, 1);

    int wb = (n * 16 + 255) / 256;        // half-warp per node
    int pb2 = (n * (HDIM / 2) + 255) / 256;
    for (int i = 0; i < 3; i++) {
        int aff = (i == 2) ? 0 : -1;   // conv3 input = extBN(gbn[0]) of conv2 output
        if (i == 2) k_prep<<<pb2, 256>>>(0, n);   // rebuild rh with extBN affine
        k_gather<<<wb, 256>>>(eps, i, aff, n);
        k_gemm_mma<64, 128, 1, 1, false, 1><<<gb, 256, SM_K64N128>>>(
            nullptr, W1 + i * HDIM * H2DIM, b1 + i * H2DIM, i, n, 0);
        k_bnprep<<<1, 128>>>(g1 + i * H2DIM, be1 + i * H2DIM, 0, i, invn);
        k_gemm_mma<128, 64, 2, 0, true, 2><<<gb, 256, SM_K128N64>>>(
            nullptr, W2 + i * H2DIM * HDIM, b2 + i * HDIM, i, n, (i == 0) ? 1 : 0);
        if (i >= 1)
            k_bnprep<<<1, 128>>>(gbn + (i - 1) * HDIM, bbn + (i - 1) * HDIM, 1, i, invn);
    }

    k_gate<<<(n * 32 + 255) / 256, 256>>>(gateW, gateb, batch, n);
    k_pool<<<(n * 32 + 255) / 256, 256>>>(batch, n);
    k_final<<<(G + 127) / 128, 128>>>(predW, predb, clsW, clsb, (float*)d_out, G);
}

// round 10
// speedup vs baseline: 1.2661x; 1.0213x over previous
#include <cuda_runtime.h>
#include <cuda_bf16.h>
#include <cuda_fp16.h>
#include <cstdint>

#define MAXN 100000
#define MAXE 3200000
#define FDIM 128
#define HDIM 64
#define H2DIM 128
#define MAXG 256
#define GROWS 128   // rows per GEMM block tile

// ---------------- device scratch (static, no allocation) ----------------
__device__ __align__(16) float d_h[(size_t)MAXN * HDIM];
__device__ __align__(16) float d_z[(size_t)MAXN * HDIM];
__device__ __align__(16) __half d_t[(size_t)MAXN * H2DIM];   // fp16 intermediate
__device__ __align__(16) __half d_rh[(size_t)MAXN * HDIM];   // relu(aff(h)) as fp16
__device__ int   d_deg[MAXN];
__device__ int   d_off[MAXN];
__device__ int   d_cur[MAXN];
__device__ int   d_csr[MAXE];
__device__ int   d_bsum[256];
__device__ int   d_boff[256];
__device__ __align__(16) float d_statTS[3 * H2DIM];
__device__ __align__(16) float d_statTQ[3 * H2DIM];
__device__ __align__(16) float d_statHS[3 * HDIM];
__device__ __align__(16) float d_statHQ[3 * HDIM];
__device__ __align__(16) float d_scE[2 * HDIM];
__device__ __align__(16) float d_shE[2 * HDIM];
__device__ unsigned d_gmax[MAXG];
__device__ float d_wsum[MAXG];
__device__ __align__(16) float d_poolS[MAXG * HDIM];
__device__ float d_gate[MAXN];

// ---------------- init ----------------
__global__ void k_init(int n, int G) {
    int stride = gridDim.x * blockDim.x;
    int i0 = blockIdx.x * blockDim.x + threadIdx.x;
    for (int i = i0; i < n; i += stride) d_deg[i] = 0;
    for (int i = i0; i < 3 * H2DIM; i += stride) { d_statTS[i] = 0.f; d_statTQ[i] = 0.f; }
    for (int i = i0; i < 3 * HDIM; i += stride) { d_statHS[i] = 0.f; d_statHQ[i] = 0.f; }
    for (int i = i0; i < G; i += stride) { d_gmax[i] = 0u; d_wsum[i] = 0.f; }
    for (int i = i0; i < G * HDIM; i += stride) d_poolS[i] = 0.f;
}

// ---------------- CSR build ----------------
__global__ void k_hist(const int* __restrict__ dst, int e) {
    int i = blockIdx.x * blockDim.x + threadIdx.x;
    if (i < e) atomicAdd(&d_deg[dst[i]], 1);
}

__global__ void k_scan1(int n) {
    __shared__ int s[1024];
    int i = blockIdx.x * 1024 + threadIdx.x;
    int v = (i < n) ? d_deg[i] : 0;
    s[threadIdx.x] = v;
    __syncthreads();
    for (int d = 1; d < 1024; d <<= 1) {
        int t = 0;
        if ((int)threadIdx.x >= d) t = s[threadIdx.x - d];
        __syncthreads();
        s[threadIdx.x] += t;
        __syncthreads();
    }
    if (i < n) d_off[i] = s[threadIdx.x] - v;
    if (threadIdx.x == 1023) d_bsum[blockIdx.x] = s[1023];
}

__global__ void k_scan2(int nb) {
    int t = threadIdx.x;
    int v = (t < nb) ? d_bsum[t] : 0;
    int orig = v;
    for (int d = 1; d < 32; d <<= 1) {
        int u = __shfl_up_sync(0xffffffffu, v, d);
        if ((t & 31) >= d) v += u;
    }
    __shared__ int ws[4];
    if ((t & 31) == 31) ws[t >> 5] = v;
    __syncthreads();
    int add = 0;
    for (int w = 0; w < (t >> 5); w++) add += ws[w];
    if (t < nb) d_boff[t] = v + add - orig;
}

__global__ void k_scan3(int n) {
    int i = blockIdx.x * blockDim.x + threadIdx.x;
    if (i < n) {
        int v = d_off[i] + d_boff[i >> 10];
        d_off[i] = v;
        d_cur[i] = v;
    }
}

__global__ void k_scatter(const int* __restrict__ src, const int* __restrict__ dst, int e) {
    int i = blockIdx.x * blockDim.x + threadIdx.x;
    if (i < e) {
        int d = dst[i];
        int p = atomicAdd(&d_cur[d], 1);
        d_csr[p] = src[i];
    }
}

// ---------------- prep: d_rh = fp16(relu(scE[idx]*h + shE[idx])) ----------------
__global__ void k_prep(int affineIdx, int n) {
    int i = blockIdx.x * blockDim.x + threadIdx.x;
    if (i >= n * (HDIM / 2)) return;
    int c = i & (HDIM / 2 - 1);
    float2 v = ((const float2*)d_h)[i];
    float2 s2 = *(const float2*)(d_scE + affineIdx * HDIM + c * 2);
    float2 h2 = *(const float2*)(d_shE + affineIdx * HDIM + c * 2);
    float rx = fmaxf(fmaf(s2.x, v.x, h2.x), 0.f);
    float ry = fmaxf(fmaf(s2.y, v.y, h2.y), 0.f);
    ((__half2*)d_rh)[i] = __floats2half2_rn(rx, ry);
}

// ---------------- gather (R7): z = (1+eps)*aff(h) + sum_in rh[src], MLP=4 ----------------
__global__ void k_gather(const float* __restrict__ epsArr, int layer, int affineIdx, int n) {
    int node = (blockIdx.x * blockDim.x + threadIdx.x) >> 5;
    int lane = threadIdx.x & 31;
    if (node >= n) return;
    const __half2* rh = (const __half2*)d_rh;
    float ax0 = 0.f, ay0 = 0.f, ax1 = 0.f, ay1 = 0.f;
    float ax2 = 0.f, ay2 = 0.f, ax3 = 0.f, ay3 = 0.f;
    int start = d_off[node], cnt = d_deg[node];
    for (int base = 0; base < cnt; base += 32) {
        int idx = 0;
        if (base + lane < cnt) idx = d_csr[start + base + lane];
        int m = min(32, cnt - base);
        int j = 0;
        for (; j + 4 <= m; j += 4) {
            int s0 = __shfl_sync(0xffffffffu, idx, j);
            int s1 = __shfl_sync(0xffffffffu, idx, j + 1);
            int s2 = __shfl_sync(0xffffffffu, idx, j + 2);
            int s3 = __shfl_sync(0xffffffffu, idx, j + 3);
            float2 f0 = __half22float2(rh[s0 * (HDIM / 2) + lane]);
            float2 f1 = __half22float2(rh[s1 * (HDIM / 2) + lane]);
            float2 f2 = __half22float2(rh[s2 * (HDIM / 2) + lane]);
            float2 f3 = __half22float2(rh[s3 * (HDIM / 2) + lane]);
            ax0 += f0.x; ay0 += f0.y;
            ax1 += f1.x; ay1 += f1.y;
            ax2 += f2.x; ay2 += f2.y;
            ax3 += f3.x; ay3 += f3.y;
        }
        for (; j < m; j++) {
            int s = __shfl_sync(0xffffffffu, idx, j);
            float2 f = __half22float2(rh[s * (HDIM / 2) + lane]);
            ax0 += f.x; ay0 += f.y;
        }
    }
    float ax = (ax0 + ax1) + (ax2 + ax3);
    float ay = (ay0 + ay1) + (ay2 + ay3);
    float sx = 1.f, sy = 1.f, hx = 0.f, hy = 0.f;
    if (affineIdx >= 0) {
        float2 s2 = *(const float2*)(d_scE + affineIdx * HDIM + lane * 2);
        float2 h2 = *(const float2*)(d_shE + affineIdx * HDIM + lane * 2);
        sx = s2.x; sy = s2.y; hx = h2.x; hy = h2.y;
    }
    float ep = 1.f + epsArr[layer];
    float2 c = *(const float2*)(d_h + (size_t)node * HDIM + lane * 2);
    float zx = fmaf(ep, fmaf(sx, c.x, hx), ax);
    float zy = fmaf(ep, fmaf(sy, c.y, hy), ay);
    *(float2*)(d_z + (size_t)node * HDIM + lane * 2) = make_float2(zx, zy);
}

// ---------------- HMMA GEMM ----------------
// 3-term bf16 split: D = Ahi@Bhi + Alo@Bhi + Ahi@Blo, fp32 accum (mma.sync m16n8k16).
// ldmatrix.x4 fragment loads. TRANS => fold BN1-prep (stats->affine) at kernel start.
__device__ __forceinline__ uint32_t bfpack(float x, float y) {
    __nv_bfloat16 bx = __float2bfloat16(x), by = __float2bfloat16(y);
    return ((uint32_t)__bfloat16_as_ushort(by) << 16) | __bfloat16_as_ushort(bx);
}
__device__ __forceinline__ uint32_t smem_u32(const void* p) {
    uint32_t a;
    asm("{ .reg .u64 t; cvta.to.shared.u64 t, %1; cvt.u32.u64 %0, t; }" : "=r"(a) : "l"(p));
    return a;
}
__device__ __forceinline__ void ldsm_x4(uint32_t& r0, uint32_t& r1, uint32_t& r2,
                                        uint32_t& r3, uint32_t addr) {
    asm volatile("ldmatrix.sync.aligned.m8n8.x4.shared.b16 {%0,%1,%2,%3}, [%4];"
                 : "=r"(r0), "=r"(r1), "=r"(r2), "=r"(r3) : "r"(addr));
}

template <int K, int N, int ASRC, int ODST, bool TRANS, int STAT>
__global__ void __launch_bounds__(256)
k_gemm_mma(const float* __restrict__ Apar, const float* __restrict__ W,
           const float* __restrict__ bias, int layer, int n, int emit_rh,
           const float* __restrict__ bng, const float* __restrict__ bnb, float invn) {
    constexpr int NT = N / 8;
    constexpr int LDIM = K + 8;
    constexpr int ASZ = GROWS * LDIM * 2;
    constexpr int BSZ = N * LDIM * 2;
    extern __shared__ __align__(16) char smem[];
    __nv_bfloat16* a_hi = (__nv_bfloat16*)(smem);
    __nv_bfloat16* a_lo = (__nv_bfloat16*)(smem + ASZ);
    __nv_bfloat16* b_hi = (__nv_bfloat16*)(smem + 2 * ASZ);
    __nv_bfloat16* b_lo = (__nv_bfloat16*)(smem + 2 * ASZ + BSZ);
    float* stS = (float*)(smem + 2 * ASZ + 2 * BSZ);   // [8][N]; start aliased as sc/sh
    float* stQ = stS + 8 * N;
    float* scS = stS;          // [128] BN scale (TRANS; consumed before stS written)
    float* shS = stS + 128;    // [128] BN shift

    int tid = threadIdx.x;
    int row0 = blockIdx.x * GROWS;

    if (TRANS) {
        if (tid < H2DIM) {
            float S = d_statTS[layer * H2DIM + tid], Q = d_statTQ[layer * H2DIM + tid];
            float mu = S * invn;
            float var = fmaf(-mu, mu, Q * invn);
            float sc = bng[tid] * rsqrtf(var + 1e-5f);
            scS[tid] = sc;
            shS[tid] = fmaf(-mu, sc, bnb[tid]);
        }
        __syncthreads();
    }

    // --- B tiles: W row-major [K][N] -> n-major bf16 hi/lo [N][LDIM] ---
    for (int idx = tid; idx < K * N; idx += 256) {
        int k = idx / N, nn = idx - k * N;
        float v = W[idx];
        __nv_bfloat16 h = __float2bfloat16(v);
        __nv_bfloat16 l = __float2bfloat16(v - __bfloat162float(h));
        b_hi[nn * LDIM + k] = h;
        b_lo[nn * LDIM + k] = l;
    }

    // --- A tile: coalesced linear load ---
    if (ASRC != 2) {
        const float* A = (ASRC == 0) ? Apar : d_z;
        for (int idx = tid; idx < GROWS * K / 4; idx += 256) {
            int row = idx / (K / 4);
            int kf = (idx - row * (K / 4)) * 4;
            int grow = row0 + row;
            float4 v = make_float4(0.f, 0.f, 0.f, 0.f);
            if (grow < n) v = *(const float4*)(A + (size_t)grow * K + kf);
            float rx = v.x - __bfloat162float(__float2bfloat16(v.x));
            float ry = v.y - __bfloat162float(__float2bfloat16(v.y));
            float rz = v.z - __bfloat162float(__float2bfloat16(v.z));
            float rw = v.w - __bfloat162float(__float2bfloat16(v.w));
            __nv_bfloat16* ah = a_hi + row * LDIM + kf;
            __nv_bfloat16* al = a_lo + row * LDIM + kf;
            *(uint32_t*)(ah) = bfpack(v.x, v.y);
            *(uint32_t*)(ah + 2) = bfpack(v.z, v.w);
            *(uint32_t*)(al) = bfpack(rx, ry);
            *(uint32_t*)(al + 2) = bfpack(rz, rw);
        }
    } else {
        const __half* A = d_t;
        for (int idx = tid; idx < GROWS * K / 8; idx += 256) {
            int row = idx / (K / 8);
            int kf = (idx - row * (K / 8)) * 8;
            int grow = row0 + row;
            uint4 raw = make_uint4(0u, 0u, 0u, 0u);
            if (grow < n) raw = *(const uint4*)(A + (size_t)grow * K + kf);
            float v[8];
            {
                float2 p0 = __half22float2(*(__half2*)&raw.x);
                float2 p1 = __half22float2(*(__half2*)&raw.y);
                float2 p2 = __half22float2(*(__half2*)&raw.z);
                float2 p3 = __half22float2(*(__half2*)&raw.w);
                v[0] = p0.x; v[1] = p0.y; v[2] = p1.x; v[3] = p1.y;
                v[4] = p2.x; v[5] = p2.y; v[6] = p3.x; v[7] = p3.y;
            }
            if (TRANS) {
#pragma unroll
                for (int j = 0; j < 8; j++)
                    v[j] = fmaxf(fmaf(scS[kf + j], v[j], shS[kf + j]), 0.f);
            }
            __nv_bfloat16* ah = a_hi + row * LDIM + kf;
            __nv_bfloat16* al = a_lo + row * LDIM + kf;
#pragma unroll
            for (int j = 0; j < 4; j++) {
                float x = v[2 * j], y = v[2 * j + 1];
                float rx = x - __bfloat162float(__float2bfloat16(x));
                float ry = y - __bfloat162float(__float2bfloat16(y));
                *(uint32_t*)(ah + 2 * j) = bfpack(x, y);
                *(uint32_t*)(al + 2 * j) = bfpack(rx, ry);
            }
        }
    }
    __syncthreads();

    int wid = tid >> 5, lane = tid & 31;
    int g = lane >> 2, tig = lane & 3;
    int wr = wid * 16;

    float acc[NT][4];
#pragma unroll
    for (int t = 0; t < NT; t++) {
        acc[t][0] = 0.f; acc[t][1] = 0.f; acc[t][2] = 0.f; acc[t][3] = 0.f;
    }

    // ldmatrix per-lane byte offsets
    uint32_t aHiA = smem_u32(a_hi), aLoA = smem_u32(a_lo);
    uint32_t bHiA = smem_u32(b_hi), bLoA = smem_u32(b_lo);
    uint32_t aOff = (uint32_t)((wr + ((lane >> 3) & 1) * 8 + (lane & 7)) * LDIM
                               + ((lane >> 4) & 1) * 8) * 2;
    uint32_t bOff = (uint32_t)((((lane >> 4) & 1) * 8 + (lane & 7)) * LDIM
                               + ((lane >> 3) & 1) * 8) * 2;

#pragma unroll
    for (int t = 0; t < 3; t++) {
        uint32_t aBase = ((t == 1) ? aLoA : aHiA) + aOff;
        uint32_t bBase = ((t == 2) ? bLoA : bHiA) + bOff;
#pragma unroll
        for (int ks = 0; ks < K / 16; ks++) {
            uint32_t ka = (uint32_t)ks * 32;
            uint32_t A0, A1, A2, A3;
            ldsm_x4(A0, A1, A2, A3, aBase + ka);
#pragma unroll
            for (int p = 0; p < NT / 2; p++) {
                uint32_t B0, B1, B2, B3;
                ldsm_x4(B0, B1, B2, B3, bBase + ka + (uint32_t)p * (16 * LDIM * 2));
                asm volatile(
                    "mma.sync.aligned.m16n8k16.row.col.f32.bf16.bf16.f32 "
                    "{%0,%1,%2,%3}, {%4,%5,%6,%7}, {%8,%9}, {%0,%1,%2,%3};"
                    : "+f"(acc[2 * p][0]), "+f"(acc[2 * p][1]),
                      "+f"(acc[2 * p][2]), "+f"(acc[2 * p][3])
                    : "r"(A0), "r"(A1), "r"(A2), "r"(A3), "r"(B0), "r"(B1));
                asm volatile(
                    "mma.sync.aligned.m16n8k16.row.col.f32.bf16.bf16.f32 "
                    "{%0,%1,%2,%3}, {%4,%5,%6,%7}, {%8,%9}, {%0,%1,%2,%3};"
                    : "+f"(acc[2 * p + 1][0]), "+f"(acc[2 * p + 1][1]),
                      "+f"(acc[2 * p + 1][2]), "+f"(acc[2 * p + 1][3])
                    : "r"(A0), "r"(A1), "r"(A2), "r"(A3), "r"(B2), "r"(B3));
            }
        }
    }

    int r0 = row0 + wr + g;
    int r1 = r0 + 8;
    bool ok0 = r0 < n, ok1 = r1 < n;
#pragma unroll
    for (int nt = 0; nt < NT; nt++) {
        int cb = nt * 8 + tig * 2;
        float bb0 = bias[cb], bb1 = bias[cb + 1];
        float v00 = acc[nt][0] + bb0, v01 = acc[nt][1] + bb1;
        float v10 = acc[nt][2] + bb0, v11 = acc[nt][3] + bb1;
        if (ODST == 0) {
            if (ok0) *(float2*)(d_h + (size_t)r0 * N + cb) = make_float2(v00, v01);
            if (ok1) *(float2*)(d_h + (size_t)r1 * N + cb) = make_float2(v10, v11);
        } else {
            __half2* op = (__half2*)d_t;
            if (ok0) op[(size_t)r0 * (N / 2) + (cb >> 1)] = __floats2half2_rn(v00, v01);
            if (ok1) op[(size_t)r1 * (N / 2) + (cb >> 1)] = __floats2half2_rn(v10, v11);
        }
        if (N == HDIM && emit_rh) {
            __half2* rhp = (__half2*)d_rh;
            if (ok0) rhp[r0 * (HDIM / 2) + (cb >> 1)] =
                __floats2half2_rn(fmaxf(v00, 0.f), fmaxf(v01, 0.f));
            if (ok1) rhp[r1 * (HDIM / 2) + (cb >> 1)] =
                __floats2half2_rn(fmaxf(v10, 0.f), fmaxf(v11, 0.f));
        }
        if (STAT) {
            float s0 = (ok0 ? v00 : 0.f) + (ok1 ? v10 : 0.f);
            float s1 = (ok0 ? v01 : 0.f) + (ok1 ? v11 : 0.f);
            float q0 = (ok0 ? v00 * v00 : 0.f) + (ok1 ? v10 * v10 : 0.f);
            float q1 = (ok0 ? v01 * v01 : 0.f) + (ok1 ? v11 * v11 : 0.f);
#pragma unroll
            for (int o = 4; o <= 16; o <<= 1) {
                s0 += __shfl_xor_sync(0xffffffffu, s0, o);
                s1 += __shfl_xor_sync(0xffffffffu, s1, o);
                q0 += __shfl_xor_sync(0xffffffffu, q0, o);
                q1 += __shfl_xor_sync(0xffffffffu, q1, o);
            }
            if (lane < 4) {
                stS[wid * N + cb] = s0;
                stS[wid * N + cb + 1] = s1;
                stQ[wid * N + cb] = q0;
                stQ[wid * N + cb + 1] = q1;
            }
        }
    }
    if (STAT) {
        __syncthreads();
        if (tid < N) {
            float s = 0.f, q = 0.f;
#pragma unroll
            for (int w = 0; w < 8; w++) { s += stS[w * N + tid]; q += stQ[w * N + tid]; }
            float* sS = (STAT == 1) ? (d_statTS + layer * H2DIM) : (d_statHS + layer * HDIM);
            float* sQ = (STAT == 1) ? (d_statTQ + layer * H2DIM) : (d_statHQ + layer * HDIM);
            atomicAdd(sS + tid, s);
            atomicAdd(sQ + tid, q);
        }
    }
}

// ---------------- external-BN affine prep (scE only) ----------------
__global__ void k_bnprep(const float* __restrict__ g, const float* __restrict__ be,
                         int layer, float invn) {
    int c = threadIdx.x;
    if (c >= HDIM) return;
    float S = d_statHS[layer * HDIM + c], Q = d_statHQ[layer * HDIM + c];
    float mu = S * invn;
    float var = fmaf(-mu, mu, Q * invn);
    float sc = g[c] * rsqrtf(var + 1e-5f);
    d_scE[(layer - 1) * HDIM + c] = sc;
    d_shE[(layer - 1) * HDIM + c] = fmaf(-mu, sc, be[c]);
}

// ---------------- attention pooling ----------------
__global__ void k_gate(const float* __restrict__ gw, const float* __restrict__ gb,
                       const int* __restrict__ batch, int n) {
    __shared__ float sgt[8];
    __shared__ int sgr[8];
    int wid = threadIdx.x >> 5;
    int node = (blockIdx.x * blockDim.x + threadIdx.x) >> 5;
    int lane = threadIdx.x & 31;
    bool act = node < n;
    float gt = -3.4e38f;
    int g = -1;
    if (act) {
        float2 s2 = *(const float2*)(d_scE + HDIM + lane * 2);
        float2 h2 = *(const float2*)(d_shE + HDIM + lane * 2);
        float2 v = *(const float2*)(d_h + (size_t)node * HDIM + lane * 2);
        float w0 = gw[lane * 2], w1 = gw[lane * 2 + 1];
        float p = fmaf(s2.x, v.x, h2.x) * w0 + fmaf(s2.y, v.y, h2.y) * w1;
        for (int o = 16; o > 0; o >>= 1) p += __shfl_xor_sync(0xffffffffu, p, o);
        gt = p + gb[0];
        g = batch[node];
        if (lane == 0) d_gate[node] = gt;
    }
    if (lane == 0) { sgt[wid] = gt; sgr[wid] = act ? g : -1; }
    __syncthreads();
    if (threadIdx.x == 0) {
        int g0 = sgr[0];
        bool uni = true;
#pragma unroll
        for (int w = 1; w < 8; w++) uni &= (sgr[w] == g0 || sgr[w] == -1);
        if (uni && g0 >= 0) {
            float mx = sgt[0];
#pragma unroll
            for (int w = 1; w < 8; w++) if (sgr[w] >= 0) mx = fmaxf(mx, sgt[w]);
            unsigned u = __float_as_uint(mx);
            unsigned enc = (u & 0x80000000u) ? ~u : (u | 0x80000000u);
            atomicMax(&d_gmax[g0], enc);
        } else {
#pragma unroll
            for (int w = 0; w < 8; w++) {
                if (sgr[w] >= 0) {
                    unsigned u = __float_as_uint(sgt[w]);
                    unsigned enc = (u & 0x80000000u) ? ~u : (u | 0x80000000u);
                    atomicMax(&d_gmax[sgr[w]], enc);
                }
            }
        }
    }
}

__global__ void k_pool(const int* __restrict__ batch, int n) {
    __shared__ float sp[8][HDIM];
    __shared__ float sw[8];
    __shared__ int sgr[8];
    int wid = threadIdx.x >> 5;
    int node = (blockIdx.x * blockDim.x + threadIdx.x) >> 5;
    int lane = threadIdx.x & 31;
    bool act = node < n;
    int g = -1;
    float c0 = 0.f, c1 = 0.f, w = 0.f;
    if (act) {
        g = batch[node];
        unsigned encm = d_gmax[g];
        float gmax = (encm & 0x80000000u) ? __uint_as_float(encm & 0x7fffffffu)
                                          : __uint_as_float(~encm);
        w = expf(d_gate[node] - gmax);
        float2 s2 = *(const float2*)(d_scE + HDIM + lane * 2);
        float2 h2 = *(const float2*)(d_shE + HDIM + lane * 2);
        float2 v = *(const float2*)(d_h + (size_t)node * HDIM + lane * 2);
        c0 = w * fmaf(s2.x, v.x, h2.x);
        c1 = w * fmaf(s2.y, v.y, h2.y);
    }
    sp[wid][lane * 2] = c0;
    sp[wid][lane * 2 + 1] = c1;
    if (lane == 0) { sw[wid] = act ? w : 0.f; sgr[wid] = act ? g : -1; }
    __syncthreads();
    int g0 = sgr[0];
    bool uni = true;
#pragma unroll
    for (int ww = 1; ww < 8; ww++) uni &= (sgr[ww] == g0 || sgr[ww] == -1);
    if (uni && g0 >= 0) {
        if (wid == 0) {
            float a0 = 0.f, a1 = 0.f;
#pragma unroll
            for (int ww = 0; ww < 8; ww++) {
                a0 += sp[ww][lane * 2];
                a1 += sp[ww][lane * 2 + 1];
            }
            atomicAdd(&d_poolS[g0 * HDIM + lane * 2], a0);
            atomicAdd(&d_poolS[g0 * HDIM + lane * 2 + 1], a1);
            if (lane == 0) {
                float ws = 0.f;
#pragma unroll
                for (int ww = 0; ww < 8; ww++) ws += sw[ww];
                atomicAdd(&d_wsum[g0], ws);
            }
        }
    } else if (act) {
        atomicAdd(&d_poolS[g * HDIM + lane * 2], c0);
        atomicAdd(&d_poolS[g * HDIM + lane * 2 + 1], c1);
        if (lane == 0) atomicAdd(&d_wsum[g], w);
    }
}

__global__ void k_final(const float* __restrict__ pW, const float* __restrict__ pb,
                        const float* __restrict__ cW, const float* __restrict__ cb,
                        float* __restrict__ out, int G) {
    int g = blockIdx.x * blockDim.x + threadIdx.x;
    if (g >= G) return;
    float inv = 1.f / d_wsum[g];
    float pooled[HDIM];
#pragma unroll
    for (int f = 0; f < HDIM; f++) pooled[f] = d_poolS[g * HDIM + f] * inv;
    float z[HDIM];
    for (int o = 0; o < HDIM; o++) {
        float a = pb[o];
        for (int i2 = 0; i2 < HDIM; i2++) a = fmaf(pooled[i2], pW[i2 * HDIM + o], a);
        z[o] = fmaxf(a, 0.f);
    }
    for (int c = 0; c < 2; c++) {
        float a = cb[c];
        for (int i2 = 0; i2 < HDIM; i2++) a = fmaf(z[i2], cW[i2 * 2 + c], a);
        out[g * 2 + c] = a;
    }
}

// ---------------- launch ----------------
extern "C" void kernel_launch(void* const* d_in, const int* in_sizes, int n_in,
                              void* d_out, int out_size) {
    const float* x     = (const float*)d_in[0];
    const float* l0W   = (const float*)d_in[1];
    const float* l0b   = (const float*)d_in[2];
    const float* eps   = (const float*)d_in[3];
    const float* W1    = (const float*)d_in[4];
    const float* b1    = (const float*)d_in[5];
    const float* g1    = (const float*)d_in[6];
    const float* be1   = (const float*)d_in[7];
    const float* W2    = (const float*)d_in[8];
    const float* b2    = (const float*)d_in[9];
    const float* gbn   = (const float*)d_in[10];
    const float* bbn   = (const float*)d_in[11];
    const float* gateW = (const float*)d_in[12];
    const float* gateb = (const float*)d_in[13];
    const float* predW = (const float*)d_in[14];
    const float* predb = (const float*)d_in[15];
    const float* clsW  = (const float*)d_in[16];
    const float* clsb  = (const float*)d_in[17];
    const int*   eidx  = (const int*)d_in[18];
    const int*   batch = (const int*)d_in[19];

    int n = in_sizes[0] / FDIM; if (n > MAXN) n = MAXN;
    int e = in_sizes[18] / 2;   if (e > MAXE) e = MAXE;
    int G = out_size / 2;       if (G > MAXG) G = MAXG;
    const int* src  = eidx;
    const int* dstp = eidx + e;
    float invn = 1.0f / (float)n;

    const int SM_K128N64 = 2 * (128 * 136 * 2) + 2 * (64 * 136 * 2) + 16 * 64 * 4;   // 108544
    const int SM_K64N128 = 2 * (128 * 72 * 2) + 2 * (128 * 72 * 2) + 16 * 128 * 4;   // 81920
    cudaFuncSetAttribute(k_gemm_mma<128, 64, 0, 0, false, 0>,
                         cudaFuncAttributeMaxDynamicSharedMemorySize, SM_K128N64);
    cudaFuncSetAttribute(k_gemm_mma<64, 128, 1, 1, false, 1>,
                         cudaFuncAttributeMaxDynamicSharedMemorySize, SM_K64N128);
    cudaFuncSetAttribute(k_gemm_mma<128, 64, 2, 0, true, 2>,
                         cudaFuncAttributeMaxDynamicSharedMemorySize, SM_K128N64);

    k_init<<<256, 256>>>(n, G);
    int eb = (e + 255) / 256;
    k_hist<<<eb, 256>>>(dstp, e);
    int nb = (n + 1023) / 1024;
    k_scan1<<<nb, 1024>>>(n);
    k_scan2<<<1, 128>>>(nb);
    k_scan3<<<(n + 255) / 256, 256>>>(n);
    k_scatter<<<eb, 256>>>(src, dstp, e);

    int gb = (n + GROWS - 1) / GROWS;
    // lin0 output feeds gather(0): emit fp16 relu copy in epilogue
    k_gemm_mma<128, 64, 0, 0, false, 0><<<gb, 256, SM_K128N64>>>(
        x, l0W, l0b, 0, n, 1, nullptr, nullptr, 0.f);

    int wb = (n * 32 + 255) / 256;
    int pb2 = (n * (HDIM / 2) + 255) / 256;
    for (int i = 0; i < 3; i++) {
        int aff = (i == 2) ? 0 : -1;   // conv3 input = extBN(gbn[0]) of conv2 output
        if (i == 2) k_prep<<<pb2, 256>>>(0, n);   // rebuild rh with extBN affine
        k_gather<<<wb, 256>>>(eps, i, aff, n);
        k_gemm_mma<64, 128, 1, 1, false, 1><<<gb, 256, SM_K64N128>>>(
            nullptr, W1 + i * HDIM * H2DIM, b1 + i * H2DIM, i, n, 0,
            nullptr, nullptr, 0.f);
        // W2 GEMM folds BN1-prep (stats -> affine) at kernel start
        k_gemm_mma<128, 64, 2, 0, true, 2><<<gb, 256, SM_K128N64>>>(
            nullptr, W2 + i * H2DIM * HDIM, b2 + i * HDIM, i, n, (i == 0) ? 1 : 0,
            g1 + i * H2DIM, be1 + i * H2DIM, invn);
        if (i >= 1)
            k_bnprep<<<1, 64>>>(gbn + (i - 1) * HDIM, bbn + (i - 1) * HDIM, i, invn);
    }

    k_gate<<<wb, 256>>>(gateW, gateb, batch, n);
    k_pool<<<wb, 256>>>(batch, n);
    k_final<<<(G + 127) / 128, 128>>>(predW, predb, clsW, clsb, (float*)d_out, G);
}